// round 6
// baseline (speedup 1.0000x reference)
#include <cuda_runtime.h>
#include <cuda_bf16.h>
#include <cstdint>

// ---------------------------------------------------------------------------
// Problem dims
// ---------------------------------------------------------------------------
#define BATCH   128
#define TSTEPS  32
#define D_DIM   6400
#define HID     1000
#define ACT     4
#define M_DIM   (BATCH * TSTEPS)   // 4096
#define N_DIM   HID                // 1000
#define N_PAD   1024               // padded N for clean tiling
#define K_DIM   D_DIM              // 6400

#define BETA_F  0.99f
#define THR_F   1.0f
#define TOL_F   1e-3f              // borderline margin -> exact fp32 recompute
#define FLAG_CAP 65536

// ---------------------------------------------------------------------------
// Global scratch (static __device__ arrays; no allocation)
// ---------------------------------------------------------------------------
__device__ float g_H1[M_DIM * N_DIM];                     // 16.4 MB

__device__ __nv_bfloat16 g_Ah[M_DIM * K_DIM];             // 52.4 MB each
__device__ __nv_bfloat16 g_Am[M_DIM * K_DIM];
__device__ __nv_bfloat16 g_Al[M_DIM * K_DIM];
__device__ __nv_bfloat16 g_Bh[N_PAD * K_DIM];             // 13.1 MB each
__device__ __nv_bfloat16 g_Bm[N_PAD * K_DIM];
__device__ __nv_bfloat16 g_Bl[N_PAD * K_DIM];

__device__ uint32_t g_spk1[M_DIM * 32];                   // bit-packed spk1 [m][32 words]
__device__ int      g_nflag;
__device__ int      g_flag[FLAG_CAP];                     // packed (b<<10)|h

// ---------------------------------------------------------------------------
// Helpers
// ---------------------------------------------------------------------------
__device__ __forceinline__ uint32_t smem_to_u32(const void* p) {
    uint32_t a;
    asm("{ .reg .u64 t; cvta.to.shared.u64 t, %1; cvt.u32.u64 %0, t; }" : "=r"(a) : "l"(p));
    return a;
}

// 3-way bf16 split of two fp32 values packed as bf16x2 (lo = elem a, hi = elem b).
__device__ __forceinline__ void split3(float a, float b,
                                       uint32_t& h, uint32_t& m, uint32_t& l) {
    uint32_t t;
    asm("cvt.rn.bf16x2.f32 %0, %1, %2;" : "=r"(t) : "f"(b), "f"(a));
    float fa = __uint_as_float(t << 16);
    float fb = __uint_as_float(t & 0xffff0000u);
    float ra = a - fa, rb = b - fb;
    h = t;
    asm("cvt.rn.bf16x2.f32 %0, %1, %2;" : "=r"(t) : "f"(rb), "f"(ra));
    fa = __uint_as_float(t << 16);
    fb = __uint_as_float(t & 0xffff0000u);
    float ra2 = ra - fa, rb2 = rb - fb;
    m = t;
    asm("cvt.rn.bf16x2.f32 %0, %1, %2;" : "=r"(t) : "f"(rb2), "f"(ra2));
    l = t;
}

__device__ __forceinline__ void cp16(uint32_t dst, const void* src) {
    asm volatile("cp.async.cg.shared.global [%0], [%1], 16;" :: "r"(dst), "l"(src));
}
#define CP_COMMIT() asm volatile("cp.async.commit_group;" ::: "memory")
#define CP_WAIT2()  asm volatile("cp.async.wait_group 2;"  ::: "memory")

__device__ __forceinline__ void ldsm4(uint32_t* d, uint32_t addr) {
    asm volatile("ldmatrix.sync.aligned.m8n8.x4.shared.b16 {%0,%1,%2,%3}, [%4];"
                 : "=r"(d[0]), "=r"(d[1]), "=r"(d[2]), "=r"(d[3]) : "r"(addr));
}

__device__ __forceinline__ void mma16816(float* c, const uint32_t* a,
                                         uint32_t b0, uint32_t b1) {
    asm volatile(
        "mma.sync.aligned.m16n8k16.row.col.f32.bf16.bf16.f32 "
        "{%0,%1,%2,%3}, {%4,%5,%6,%7}, {%8,%9}, {%0,%1,%2,%3};"
        : "+f"(c[0]), "+f"(c[1]), "+f"(c[2]), "+f"(c[3])
        : "r"(a[0]), "r"(a[1]), "r"(a[2]), "r"(a[3]), "r"(b0), "r"(b1));
}

// ---------------------------------------------------------------------------
// Split kernels: fp32 -> (hi, mid, lo) bf16
// ---------------------------------------------------------------------------
__global__ __launch_bounds__(256)
void split_x_kernel(const float* __restrict__ X)
{
    const size_t w = (size_t)blockIdx.x * 256 + threadIdx.x;
    if (w >= (size_t)M_DIM * K_DIM / 2) return;
    const float2 v = ((const float2*)X)[w];
    uint32_t h, m, l;
    split3(v.x, v.y, h, m, l);
    ((uint32_t*)g_Ah)[w] = h;
    ((uint32_t*)g_Am)[w] = m;
    ((uint32_t*)g_Al)[w] = l;
}

__global__ __launch_bounds__(256)
void split_w_kernel(const float* __restrict__ W1)
{
    const size_t w = (size_t)blockIdx.x * 256 + threadIdx.x;
    if (w >= (size_t)N_PAD * K_DIM / 2) return;
    const size_t row = (w * 2) / K_DIM;
    uint32_t h = 0, m = 0, l = 0;
    if (row < N_DIM) {
        const float2 v = ((const float2*)W1)[w];
        split3(v.x, v.y, h, m, l);
    }
    ((uint32_t*)g_Bh)[w] = h;
    ((uint32_t*)g_Bm)[w] = m;
    ((uint32_t*)g_Bl)[w] = l;
}

__global__ void zero_flags_kernel() { g_nflag = 0; }

// ---------------------------------------------------------------------------
// GEMM: H1 = X @ W1^T + b1 via HMMA bf16x3 (6 error-split passes)
// ---------------------------------------------------------------------------
#define BM 128
#define BN 128
#define BK 32
#define STAGES 4
#define KTILES (K_DIM / BK)        // 200
#define SPLIT_SM 8192              // 128 rows x 64 B
#define STAGE_SM (6 * SPLIT_SM)    // 49152 B
#define GEMM_SMEM (STAGES * STAGE_SM)  // 196608 B

#define SWZ(r, c) (((r) << 6) + (((c) ^ (((r) >> 1) & 3)) << 4))

__global__ __launch_bounds__(256, 1)
void gemm_h1_hmma(const float* __restrict__ bias)
{
    extern __shared__ char smem[];
    const uint32_t smb = smem_to_u32(smem);
    const int tid  = threadIdx.x;
    const int wid  = tid >> 5;
    const int lane = tid & 31;
    const int bm = blockIdx.y * BM;
    const int bn = blockIdx.x * BN;
    const int warp_m = (wid >> 2) * 64;
    const int warp_n = (wid & 3) * 32;

    const __nv_bfloat16* bases[6] = { g_Ah, g_Am, g_Al, g_Bh, g_Bm, g_Bl };
    uint32_t soff[12];
    const __nv_bfloat16* gptr[12];
#pragma unroll
    for (int i = 0; i < 12; ++i) {
        const int idx = tid + i * 256;
        const int s = idx >> 9;
        const int r = (idx >> 2) & 127;
        const int c = idx & 3;
        soff[i] = (uint32_t)(s * SPLIT_SM + SWZ(r, c));
        const int rowg = (s < 3 ? bm : bn) + r;
        gptr[i] = bases[s] + (size_t)rowg * K_DIM + c * 8;
    }

    float acc[4][4][4];
#pragma unroll
    for (int mt = 0; mt < 4; ++mt)
#pragma unroll
        for (int nt = 0; nt < 4; ++nt)
#pragma unroll
            for (int e = 0; e < 4; ++e) acc[mt][nt][e] = 0.0f;

#pragma unroll
    for (int s = 0; s < STAGES - 1; ++s) {
        const uint32_t stb = smb + s * STAGE_SM;
        const int koff = s * BK;
#pragma unroll
        for (int i = 0; i < 12; ++i) cp16(stb + soff[i], gptr[i] + koff);
        CP_COMMIT();
    }

    const int lr  = lane & 15;
    const int lch = lane >> 4;

    for (int kt = 0; kt < KTILES; ++kt) {
        CP_WAIT2();
        __syncthreads();

        const int nk = kt + STAGES - 1;
        if (nk < KTILES) {
            const uint32_t stb = smb + (nk & 3) * STAGE_SM;
            const int koff = nk * BK;
#pragma unroll
            for (int i = 0; i < 12; ++i) cp16(stb + soff[i], gptr[i] + koff);
        }
        CP_COMMIT();

        const uint32_t stb = smb + (kt & 3) * STAGE_SM;

#pragma unroll
        for (int k16 = 0; k16 < 2; ++k16) {
            const int c = k16 * 2 + lch;
            uint32_t af[3][4][4];
#pragma unroll
            for (int sp = 0; sp < 3; ++sp) {
                const uint32_t base = stb + sp * SPLIT_SM;
#pragma unroll
                for (int mt = 0; mt < 4; ++mt) {
                    const int r = warp_m + mt * 16 + lr;
                    ldsm4(af[sp][mt], base + SWZ(r, c));
                }
            }
            uint32_t bf[3][2][4];
#pragma unroll
            for (int sp = 0; sp < 3; ++sp) {
                const uint32_t base = stb + (3 + sp) * SPLIT_SM;
#pragma unroll
                for (int np = 0; np < 2; ++np) {
                    const int r = warp_n + np * 16 + lr;
                    ldsm4(bf[sp][np], base + SWZ(r, c));
                }
            }
            const int pa[6] = {0, 0, 1, 0, 2, 1};
            const int pb[6] = {0, 1, 0, 2, 0, 1};
#pragma unroll
            for (int p = 0; p < 6; ++p) {
                const int asp = pa[p], bsp = pb[p];
#pragma unroll
                for (int mt = 0; mt < 4; ++mt) {
#pragma unroll
                    for (int nt = 0; nt < 4; ++nt) {
                        const int np = nt >> 1, sel = nt & 1;
                        mma16816(acc[mt][nt], af[asp][mt],
                                 bf[bsp][np][sel], bf[bsp][np][sel + 2]);
                    }
                }
            }
        }
    }

    const int lrow = lane >> 2;
    const int lcol = (lane & 3) * 2;
#pragma unroll
    for (int nt = 0; nt < 4; ++nt) {
        const int n0 = bn + warp_n + nt * 8;
        if (n0 >= N_DIM) continue;
        const int nc = n0 + lcol;
        const float bx = bias[nc], by = bias[nc + 1];
#pragma unroll
        for (int mt = 0; mt < 4; ++mt) {
            const int m0 = bm + warp_m + mt * 16 + lrow;
            float2 v0 = make_float2(acc[mt][nt][0] + bx, acc[mt][nt][1] + by);
            float2 v1 = make_float2(acc[mt][nt][2] + bx, acc[mt][nt][3] + by);
            *(float2*)&g_H1[(size_t)m0 * N_DIM + nc]       = v0;
            *(float2*)&g_H1[(size_t)(m0 + 8) * N_DIM + nc] = v1;
        }
    }
}

// ---------------------------------------------------------------------------
// Layer-1 scan: LIF on HMMA h1 -> bit-packed spk1 + borderline flags.
// One block per b; thread covers h = tid + j*256.
// ---------------------------------------------------------------------------
__global__ __launch_bounds__(256)
void snn_scan_kernel()
{
    const int b    = blockIdx.x;
    const int tid  = threadIdx.x;
    const int lane = tid & 31;
    const int warp = tid >> 5;

    float m1[4] = {0.f, 0.f, 0.f, 0.f};
    int   flg[4] = {0, 0, 0, 0};

    for (int t = 0; t < TSTEPS; t++) {
        const int m = b * TSTEPS + t;
        const float* h1row = g_H1 + (size_t)m * HID;
#pragma unroll
        for (int j = 0; j < 4; j++) {
            const int h = tid + j * 256;
            const bool valid = (h < HID);
            const float cur = valid ? h1row[h] : 0.0f;
            const float mn  = (m1[j] > THR_F) ? 0.0f : fmaf(BETA_F, m1[j], cur);
            m1[j] = mn;
            const bool spk = valid && (mn > THR_F);
            if (valid && fabsf(mn - THR_F) < TOL_F) flg[j] = 1;
            const uint32_t bits = __ballot_sync(0xffffffffu, spk);
            if (lane == 0) g_spk1[m * 32 + j * 8 + warp] = bits;
        }
    }

#pragma unroll
    for (int j = 0; j < 4; j++) {
        const int h = tid + j * 256;
        if (flg[j] && h < HID) {
            const int i = atomicAdd(&g_nflag, 1);
            if (i < FLAG_CAP) g_flag[i] = (b << 10) | h;
        }
    }
}

// ---------------------------------------------------------------------------
// Fixup: exact fp32 recompute of flagged (b,h) pairs; rewrite spk1 bits.
// One warp per list entry (strided).
// ---------------------------------------------------------------------------
__global__ __launch_bounds__(256)
void snn_fixup_kernel(const float* __restrict__ X,
                      const float* __restrict__ W1,
                      const float* __restrict__ b1)
{
    const int lane   = threadIdx.x & 31;
    const int gwarp  = (blockIdx.x * blockDim.x + threadIdx.x) >> 5;
    const int nwarps = (gridDim.x * blockDim.x) >> 5;
    int total = g_nflag;
    if (total > FLAG_CAP) total = FLAG_CAP;

    for (int e = gwarp; e < total; e += nwarps) {
        const int pair = g_flag[e];
        const int b = pair >> 10;
        const int h = pair & 1023;
        const float* wrow = W1 + (size_t)h * K_DIM;
        const float  bv   = b1[h];

        float mem = 0.0f;
        for (int t = 0; t < TSTEPS; t++) {
            const float* xrow = X + (size_t)(b * TSTEPS + t) * K_DIM;
            float s = 0.0f;
            for (int k = lane * 4; k < K_DIM; k += 128) {
                const float4 xv = *(const float4*)(xrow + k);
                const float4 wv = *(const float4*)(wrow + k);
                s = fmaf(xv.x, wv.x, s);
                s = fmaf(xv.y, wv.y, s);
                s = fmaf(xv.z, wv.z, s);
                s = fmaf(xv.w, wv.w, s);
            }
#pragma unroll
            for (int o = 16; o; o >>= 1) s += __shfl_xor_sync(0xffffffffu, s, o);

            const float cur = s + bv;
            const float mn  = (mem > THR_F) ? 0.0f : fmaf(BETA_F, mem, cur);
            mem = mn;
            if (lane == 0) {
                uint32_t* wptr = &g_spk1[(size_t)(b * TSTEPS + t) * 32 + (h >> 5)];
                const uint32_t bit = 1u << (h & 31);
                if (mn > THR_F) atomicOr(wptr, bit);
                else            atomicAnd(wptr, ~bit);
            }
        }
    }
}

// ---------------------------------------------------------------------------
// Layer-2: h2 = spk1 @ W2^T + b2, LIF, write spikes.
// ---------------------------------------------------------------------------
__global__ __launch_bounds__(256)
void snn_layer2_kernel(const float* __restrict__ W2,
                       const float* __restrict__ b2,
                       float* __restrict__ out)
{
    __shared__ float sW2[ACT][HID];
    __shared__ float sred[8][ACT];

    const int b    = blockIdx.x;
    const int tid  = threadIdx.x;
    const int lane = tid & 31;
    const int warp = tid >> 5;

    for (int i = tid; i < ACT * HID; i += 256)
        sW2[i / HID][i % HID] = W2[i];
    __syncthreads();

    float m2[ACT] = {0.f, 0.f, 0.f, 0.f};

    for (int t = 0; t < TSTEPS; t++) {
        const int m = b * TSTEPS + t;
        float acc0 = 0.f, acc1 = 0.f, acc2 = 0.f, acc3 = 0.f;

#pragma unroll
        for (int j = 0; j < 4; j++) {
            const int h = tid + j * 256;
            if (h < HID) {
                const uint32_t bits = g_spk1[m * 32 + (h >> 5)];
                const float spk = (float)((bits >> (h & 31)) & 1u);
                acc0 = fmaf(spk, sW2[0][h], acc0);
                acc1 = fmaf(spk, sW2[1][h], acc1);
                acc2 = fmaf(spk, sW2[2][h], acc2);
                acc3 = fmaf(spk, sW2[3][h], acc3);
            }
        }

#pragma unroll
        for (int o = 16; o; o >>= 1) {
            acc0 += __shfl_xor_sync(0xffffffffu, acc0, o);
            acc1 += __shfl_xor_sync(0xffffffffu, acc1, o);
            acc2 += __shfl_xor_sync(0xffffffffu, acc2, o);
            acc3 += __shfl_xor_sync(0xffffffffu, acc3, o);
        }
        if (lane == 0) {
            sred[warp][0] = acc0; sred[warp][1] = acc1;
            sred[warp][2] = acc2; sred[warp][3] = acc3;
        }
        __syncthreads();

        if (tid == 0) {
#pragma unroll
            for (int a = 0; a < ACT; a++) {
                float h2 = b2[a];
#pragma unroll
                for (int w = 0; w < 8; w++) h2 += sred[w][a];
                const float mn = (m2[a] > THR_F) ? 0.0f : fmaf(BETA_F, m2[a], h2);
                m2[a] = mn;
                out[((size_t)m) * ACT + a] = (mn > THR_F) ? 1.0f : 0.0f;
            }
        }
        __syncthreads();
    }
}

// ---------------------------------------------------------------------------
extern "C" void kernel_launch(void* const* d_in, const int* in_sizes, int n_in,
                              void* d_out, int out_size)
{
    const float* x  = (const float*)d_in[0];   // [128,32,6400]
    const float* W1 = (const float*)d_in[1];   // [1000,6400]
    const float* b1 = (const float*)d_in[2];   // [1000]
    const float* W2 = (const float*)d_in[3];   // [4,1000]
    const float* b2 = (const float*)d_in[4];   // [4]
    float* out = (float*)d_out;                // [128,32,4]

    cudaFuncSetAttribute(gemm_h1_hmma,
                         cudaFuncAttributeMaxDynamicSharedMemorySize, GEMM_SMEM);

    {   // split X -> hi/mid/lo bf16
        const int nwords = M_DIM * K_DIM / 2;
        split_x_kernel<<<(nwords + 255) / 256, 256>>>(x);
    }
    {   // split W1 (padded to 1024 rows)
        const int nwords = N_PAD * K_DIM / 2;
        split_w_kernel<<<(nwords + 255) / 256, 256>>>(W1);
    }

    dim3 grid(N_PAD / BN, M_DIM / BM);         // (8, 32)
    gemm_h1_hmma<<<grid, 256, GEMM_SMEM>>>(b1);

    zero_flags_kernel<<<1, 1>>>();
    snn_scan_kernel<<<BATCH, 256>>>();
    snn_fixup_kernel<<<256, 256>>>(x, W1, b1);
    snn_layer2_kernel<<<BATCH, 256>>>(W2, b2, out);
}

// round 7
// speedup vs baseline: 1.4764x; 1.4764x over previous
#include <cuda_runtime.h>
#include <cuda_bf16.h>
#include <cstdint>

// ---------------------------------------------------------------------------
// Problem dims
// ---------------------------------------------------------------------------
#define BATCH   128
#define TSTEPS  32
#define D_DIM   6400
#define HID     1000
#define ACT     4
#define M_DIM   (BATCH * TSTEPS)   // 4096
#define N_DIM   HID                // 1000
#define N_PAD   1024
#define K_DIM   D_DIM              // 6400

#define BETA_F  0.99f
#define THR_F   1.0f
#define TOL_F   1e-3f              // borderline margin -> exact fp32 recompute
#define FLAG_CAP 65536

// ---------------------------------------------------------------------------
// Global scratch
// ---------------------------------------------------------------------------
__device__ float g_H1[M_DIM * N_DIM];                     // 16.4 MB

__device__ __nv_bfloat16 g_Ah[M_DIM * K_DIM];             // 52.4 MB each
__device__ __nv_bfloat16 g_Am[M_DIM * K_DIM];
__device__ __nv_bfloat16 g_Bh[N_PAD * K_DIM];             // 13.1 MB each
__device__ __nv_bfloat16 g_Bm[N_PAD * K_DIM];

__device__ uint32_t g_spk1[M_DIM * 32];                   // bit-packed spk1
__device__ int      g_nflag;
__device__ int      g_flag[FLAG_CAP];                     // packed (b<<10)|h

// ---------------------------------------------------------------------------
// Helpers
// ---------------------------------------------------------------------------
__device__ __forceinline__ uint32_t smem_to_u32(const void* p) {
    uint32_t a;
    asm("{ .reg .u64 t; cvta.to.shared.u64 t, %1; cvt.u32.u64 %0, t; }" : "=r"(a) : "l"(p));
    return a;
}

// 2-way bf16 split of two fp32 values packed as bf16x2 (lo = elem a, hi = elem b).
__device__ __forceinline__ void split2(float a, float b, uint32_t& h, uint32_t& m) {
    uint32_t t;
    asm("cvt.rn.bf16x2.f32 %0, %1, %2;" : "=r"(t) : "f"(b), "f"(a));
    float fa = __uint_as_float(t << 16);
    float fb = __uint_as_float(t & 0xffff0000u);
    float ra = a - fa, rb = b - fb;
    h = t;
    asm("cvt.rn.bf16x2.f32 %0, %1, %2;" : "=r"(t) : "f"(rb), "f"(ra));
    m = t;
}

__device__ __forceinline__ void cp16(uint32_t dst, const void* src) {
    asm volatile("cp.async.cg.shared.global [%0], [%1], 16;" :: "r"(dst), "l"(src));
}
#define CP_COMMIT() asm volatile("cp.async.commit_group;" ::: "memory")
#define CP_WAIT2()  asm volatile("cp.async.wait_group 2;"  ::: "memory")

__device__ __forceinline__ void ldsm4(uint32_t* d, uint32_t addr) {
    asm volatile("ldmatrix.sync.aligned.m8n8.x4.shared.b16 {%0,%1,%2,%3}, [%4];"
                 : "=r"(d[0]), "=r"(d[1]), "=r"(d[2]), "=r"(d[3]) : "r"(addr));
}

__device__ __forceinline__ void mma16816(float* c, const uint32_t* a,
                                         uint32_t b0, uint32_t b1) {
    asm volatile(
        "mma.sync.aligned.m16n8k16.row.col.f32.bf16.bf16.f32 "
        "{%0,%1,%2,%3}, {%4,%5,%6,%7}, {%8,%9}, {%0,%1,%2,%3};"
        : "+f"(c[0]), "+f"(c[1]), "+f"(c[2]), "+f"(c[3])
        : "r"(a[0]), "r"(a[1]), "r"(a[2]), "r"(a[3]), "r"(b0), "r"(b1));
}

// ---------------------------------------------------------------------------
// Split kernels: fp32 -> (hi, mid) bf16
// ---------------------------------------------------------------------------
__global__ __launch_bounds__(256)
void split_x_kernel(const float* __restrict__ X)
{
    const size_t w = (size_t)blockIdx.x * 256 + threadIdx.x;
    if (w >= (size_t)M_DIM * K_DIM / 2) return;
    const float2 v = ((const float2*)X)[w];
    uint32_t h, m;
    split2(v.x, v.y, h, m);
    ((uint32_t*)g_Ah)[w] = h;
    ((uint32_t*)g_Am)[w] = m;
}

__global__ __launch_bounds__(256)
void split_w_kernel(const float* __restrict__ W1)
{
    if (blockIdx.x == 0 && threadIdx.x == 0) g_nflag = 0;   // fold flag reset in
    const size_t w = (size_t)blockIdx.x * 256 + threadIdx.x;
    if (w >= (size_t)N_PAD * K_DIM / 2) return;
    const size_t row = (w * 2) / K_DIM;
    uint32_t h = 0, m = 0;
    if (row < N_DIM) {
        const float2 v = ((const float2*)W1)[w];
        split2(v.x, v.y, h, m);
    }
    ((uint32_t*)g_Bh)[w] = h;
    ((uint32_t*)g_Bm)[w] = m;
}

// ---------------------------------------------------------------------------
// GEMM: H1 = X @ W1^T + b1 via HMMA bf16x2 (3 error-split passes)
// BM=128 BN=128 BK=32, 512 threads (16 warps, 64x16 warp tiles), 4-stage
// cp.async pipeline, XOR-swizzled 64B smem rows.
// ---------------------------------------------------------------------------
#define BM 128
#define BN 128
#define BK 32
#define STAGES 4
#define KTILES (K_DIM / BK)        // 200
#define SPLIT_SM 8192              // 128 rows x 64 B
#define STAGE_SM (4 * SPLIT_SM)    // 32768 B : Ah, Am, Bh, Bm
#define GEMM_SMEM (STAGES * STAGE_SM)  // 131072 B

#define SWZ(r, c) (((r) << 6) + (((c) ^ (((r) >> 1) & 3)) << 4))

__global__ __launch_bounds__(512, 1)
void gemm_h1_hmma(const float* __restrict__ bias)
{
    extern __shared__ char smem[];
    const uint32_t smb = smem_to_u32(smem);
    const int tid  = threadIdx.x;
    const int wid  = tid >> 5;
    const int lane = tid & 31;
    const int bm = blockIdx.y * BM;
    const int bn = blockIdx.x * BN;
    const int warp_m = (wid >> 3) * 64;   // 0 or 64
    const int warp_n = (wid & 7) * 16;    // 0..112

    // cp.async plan: 2048 16B-chunks per stage, 4 per thread.
    // idx = tid + i*512; s = idx>>9 (0:Ah 1:Am 2:Bh 3:Bm), r=(idx>>2)&127, c=idx&3
    const __nv_bfloat16* bases[4] = { g_Ah, g_Am, g_Bh, g_Bm };
    uint32_t soff[4];
    const __nv_bfloat16* gptr[4];
#pragma unroll
    for (int i = 0; i < 4; ++i) {
        const int idx = tid + i * 512;
        const int s = idx >> 9;
        const int r = (idx >> 2) & 127;
        const int c = idx & 3;
        soff[i] = (uint32_t)(s * SPLIT_SM + SWZ(r, c));
        const int rowg = (s < 2 ? bm : bn) + r;
        gptr[i] = bases[s] + (size_t)rowg * K_DIM + c * 8;
    }

    float acc[4][2][4];
#pragma unroll
    for (int mt = 0; mt < 4; ++mt)
#pragma unroll
        for (int nt = 0; nt < 2; ++nt)
#pragma unroll
            for (int e = 0; e < 4; ++e) acc[mt][nt][e] = 0.0f;

    // prologue: prefetch stages 0..2
#pragma unroll
    for (int s = 0; s < STAGES - 1; ++s) {
        const uint32_t stb = smb + s * STAGE_SM;
        const int koff = s * BK;
#pragma unroll
        for (int i = 0; i < 4; ++i) cp16(stb + soff[i], gptr[i] + koff);
        CP_COMMIT();
    }

    const int lr  = lane & 15;
    const int lch = lane >> 4;

    for (int kt = 0; kt < KTILES; ++kt) {
        CP_WAIT2();
        __syncthreads();

        const int nk = kt + STAGES - 1;
        if (nk < KTILES) {
            const uint32_t stb = smb + (nk & 3) * STAGE_SM;
            const int koff = nk * BK;
#pragma unroll
            for (int i = 0; i < 4; ++i) cp16(stb + soff[i], gptr[i] + koff);
        }
        CP_COMMIT();

        const uint32_t stb = smb + (kt & 3) * STAGE_SM;

#pragma unroll
        for (int k16 = 0; k16 < 2; ++k16) {
            const int c = k16 * 2 + lch;
            // A fragments: hi, mid
            uint32_t af[2][4][4];
#pragma unroll
            for (int sp = 0; sp < 2; ++sp) {
                const uint32_t base = stb + sp * SPLIT_SM;
#pragma unroll
                for (int mt = 0; mt < 4; ++mt)
                    ldsm4(af[sp][mt], base + SWZ(warp_m + mt * 16 + lr, c));
            }
            // B fragments: hi, mid (one 16-row group per warp)
            uint32_t bf[2][4];
#pragma unroll
            for (int sp = 0; sp < 2; ++sp)
                ldsm4(bf[sp], stb + (2 + sp) * SPLIT_SM + SWZ(warp_n + lr, c));

            // 3 passes: (A,B) in { (h,h), (h,m), (m,h) }
            const int pa[3] = {0, 0, 1};
            const int pb[3] = {0, 1, 0};
#pragma unroll
            for (int p = 0; p < 3; ++p) {
#pragma unroll
                for (int mt = 0; mt < 4; ++mt) {
#pragma unroll
                    for (int nt = 0; nt < 2; ++nt)
                        mma16816(acc[mt][nt], af[pa[p]][mt],
                                 bf[pb[p]][nt], bf[pb[p]][nt + 2]);
                }
            }
        }
    }

    // epilogue: add bias, store fp32 to g_H1
    const int lrow = lane >> 2;
    const int lcol = (lane & 3) * 2;
#pragma unroll
    for (int nt = 0; nt < 2; ++nt) {
        const int n0 = bn + warp_n + nt * 8;
        if (n0 >= N_DIM) continue;
        const int nc = n0 + lcol;
        const float bx = bias[nc], by = bias[nc + 1];
#pragma unroll
        for (int mt = 0; mt < 4; ++mt) {
            const int m0 = bm + warp_m + mt * 16 + lrow;
            float2 v0 = make_float2(acc[mt][nt][0] + bx, acc[mt][nt][1] + by);
            float2 v1 = make_float2(acc[mt][nt][2] + bx, acc[mt][nt][3] + by);
            *(float2*)&g_H1[(size_t)m0 * N_DIM + nc]       = v0;
            *(float2*)&g_H1[(size_t)(m0 + 8) * N_DIM + nc] = v1;
        }
    }
}

// ---------------------------------------------------------------------------
// Layer-1 scan: LIF on HMMA h1 -> bit-packed spk1 + borderline flags.
// grid (BATCH, 4): block = 256 h-values; next-t prefetch.
// ---------------------------------------------------------------------------
__global__ __launch_bounds__(256)
void snn_scan_kernel()
{
    const int b    = blockIdx.x;
    const int hc   = blockIdx.y;
    const int tid  = threadIdx.x;
    const int lane = tid & 31;
    const int warp = tid >> 5;
    const int h    = hc * 256 + tid;
    const bool valid = (h < HID);

    float m1 = 0.0f;
    int flg = 0;

    float cur_next = valid ? g_H1[(size_t)(b * TSTEPS) * HID + h] : 0.0f;

    for (int t = 0; t < TSTEPS; t++) {
        const int m = b * TSTEPS + t;
        const float cur = cur_next;
        if (t + 1 < TSTEPS)
            cur_next = valid ? g_H1[(size_t)(m + 1) * HID + h] : 0.0f;

        const float mn = (m1 > THR_F) ? 0.0f : fmaf(BETA_F, m1, cur);
        m1 = mn;
        const bool spk = valid && (mn > THR_F);
        if (valid && fabsf(mn - THR_F) < TOL_F) flg = 1;
        const uint32_t bits = __ballot_sync(0xffffffffu, spk);
        if (lane == 0) g_spk1[m * 32 + hc * 8 + warp] = bits;
    }

    if (flg && valid) {
        const int i = atomicAdd(&g_nflag, 1);
        if (i < FLAG_CAP) g_flag[i] = (b << 10) | h;
    }
}

// ---------------------------------------------------------------------------
// Fixup: exact fp32 recompute of flagged (b,h) pairs; rewrite spk1 bits.
// ---------------------------------------------------------------------------
__global__ __launch_bounds__(256)
void snn_fixup_kernel(const float* __restrict__ X,
                      const float* __restrict__ W1,
                      const float* __restrict__ b1)
{
    const int lane   = threadIdx.x & 31;
    const int gwarp  = (blockIdx.x * blockDim.x + threadIdx.x) >> 5;
    const int nwarps = (gridDim.x * blockDim.x) >> 5;
    int total = g_nflag;
    if (total > FLAG_CAP) total = FLAG_CAP;

    for (int e = gwarp; e < total; e += nwarps) {
        const int pair = g_flag[e];
        const int b = pair >> 10;
        const int h = pair & 1023;
        const float* wrow = W1 + (size_t)h * K_DIM;
        const float  bv   = b1[h];

        float mem = 0.0f;
        for (int t = 0; t < TSTEPS; t++) {
            const float* xrow = X + (size_t)(b * TSTEPS + t) * K_DIM;
            float s = 0.0f;
            for (int k = lane * 4; k < K_DIM; k += 128) {
                const float4 xv = *(const float4*)(xrow + k);
                const float4 wv = *(const float4*)(wrow + k);
                s = fmaf(xv.x, wv.x, s);
                s = fmaf(xv.y, wv.y, s);
                s = fmaf(xv.z, wv.z, s);
                s = fmaf(xv.w, wv.w, s);
            }
#pragma unroll
            for (int o = 16; o; o >>= 1) s += __shfl_xor_sync(0xffffffffu, s, o);

            const float cur = s + bv;
            const float mn  = (mem > THR_F) ? 0.0f : fmaf(BETA_F, mem, cur);
            mem = mn;
            if (lane == 0) {
                uint32_t* wptr = &g_spk1[(size_t)(b * TSTEPS + t) * 32 + (h >> 5)];
                const uint32_t bit = 1u << (h & 31);
                if (mn > THR_F) atomicOr(wptr, bit);
                else            atomicAnd(wptr, ~bit);
            }
        }
    }
}

// ---------------------------------------------------------------------------
// Layer-2: h2 = spk1 @ W2^T + b2, LIF, write spikes.
// ---------------------------------------------------------------------------
__global__ __launch_bounds__(256)
void snn_layer2_kernel(const float* __restrict__ W2,
                       const float* __restrict__ b2,
                       float* __restrict__ out)
{
    __shared__ float sW2[ACT][HID];
    __shared__ float sred[8][ACT];

    const int b    = blockIdx.x;
    const int tid  = threadIdx.x;
    const int lane = tid & 31;
    const int warp = tid >> 5;

    for (int i = tid; i < ACT * HID; i += 256)
        sW2[i / HID][i % HID] = W2[i];
    __syncthreads();

    float m2[ACT] = {0.f, 0.f, 0.f, 0.f};

    for (int t = 0; t < TSTEPS; t++) {
        const int m = b * TSTEPS + t;
        float acc0 = 0.f, acc1 = 0.f, acc2 = 0.f, acc3 = 0.f;

#pragma unroll
        for (int j = 0; j < 4; j++) {
            const int h = tid + j * 256;
            if (h < HID) {
                const uint32_t bits = g_spk1[m * 32 + (h >> 5)];
                const float spk = (float)((bits >> (h & 31)) & 1u);
                acc0 = fmaf(spk, sW2[0][h], acc0);
                acc1 = fmaf(spk, sW2[1][h], acc1);
                acc2 = fmaf(spk, sW2[2][h], acc2);
                acc3 = fmaf(spk, sW2[3][h], acc3);
            }
        }

#pragma unroll
        for (int o = 16; o; o >>= 1) {
            acc0 += __shfl_xor_sync(0xffffffffu, acc0, o);
            acc1 += __shfl_xor_sync(0xffffffffu, acc1, o);
            acc2 += __shfl_xor_sync(0xffffffffu, acc2, o);
            acc3 += __shfl_xor_sync(0xffffffffu, acc3, o);
        }
        if (lane == 0) {
            sred[warp][0] = acc0; sred[warp][1] = acc1;
            sred[warp][2] = acc2; sred[warp][3] = acc3;
        }
        __syncthreads();

        if (tid == 0) {
#pragma unroll
            for (int a = 0; a < ACT; a++) {
                float h2 = b2[a];
#pragma unroll
                for (int w = 0; w < 8; w++) h2 += sred[w][a];
                const float mn = (m2[a] > THR_F) ? 0.0f : fmaf(BETA_F, m2[a], h2);
                m2[a] = mn;
                out[((size_t)m) * ACT + a] = (mn > THR_F) ? 1.0f : 0.0f;
            }
        }
        __syncthreads();
    }
}

// ---------------------------------------------------------------------------
extern "C" void kernel_launch(void* const* d_in, const int* in_sizes, int n_in,
                              void* d_out, int out_size)
{
    const float* x  = (const float*)d_in[0];   // [128,32,6400]
    const float* W1 = (const float*)d_in[1];   // [1000,6400]
    const float* b1 = (const float*)d_in[2];   // [1000]
    const float* W2 = (const float*)d_in[3];   // [4,1000]
    const float* b2 = (const float*)d_in[4];   // [4]
    float* out = (float*)d_out;                // [128,32,4]

    cudaFuncSetAttribute(gemm_h1_hmma,
                         cudaFuncAttributeMaxDynamicSharedMemorySize, GEMM_SMEM);

    {   // split X -> hi/mid bf16
        const int nwords = M_DIM * K_DIM / 2;
        split_x_kernel<<<(nwords + 255) / 256, 256>>>(x);
    }
    {   // split W1 (padded) -> hi/mid bf16 ; also resets flag counter
        const int nwords = N_PAD * K_DIM / 2;
        split_w_kernel<<<(nwords + 255) / 256, 256>>>(W1);
    }

    dim3 grid(N_PAD / BN, M_DIM / BM);         // (8, 32)
    gemm_h1_hmma<<<grid, 512, GEMM_SMEM>>>(b1);

    dim3 sgrid(BATCH, 4);
    snn_scan_kernel<<<sgrid, 256>>>();
    snn_fixup_kernel<<<256, 256>>>(x, W1, b1);
    snn_layer2_kernel<<<BATCH, 256>>>(W2, b2, out);
}

// round 8
// speedup vs baseline: 1.4848x; 1.0057x over previous
#include <cuda_runtime.h>
#include <cuda_bf16.h>
#include <cstdint>

// ---------------------------------------------------------------------------
// Problem dims
// ---------------------------------------------------------------------------
#define BATCH   128
#define TSTEPS  32
#define D_DIM   6400
#define HID     1000
#define ACT     4
#define M_DIM   (BATCH * TSTEPS)   // 4096
#define N_DIM   HID                // 1000
#define N_PAD   1024
#define K_DIM   D_DIM              // 6400

#define BETA_F  0.99f
#define THR_F   1.0f
#define TOL_F   2.5e-4f            // borderline margin -> exact fp32 recompute
#define FLAG_CAP 65536

// ---------------------------------------------------------------------------
// Global scratch
// ---------------------------------------------------------------------------
__device__ __nv_bfloat16 g_Ah[M_DIM * K_DIM];             // 52.4 MB each
__device__ __nv_bfloat16 g_Am[M_DIM * K_DIM];
__device__ __nv_bfloat16 g_Bh[N_PAD * K_DIM];             // 13.1 MB each
__device__ __nv_bfloat16 g_Bm[N_PAD * K_DIM];

__device__ uint32_t g_spk1[M_DIM * 32];                   // bit-packed spk1
__device__ int      g_nflag;
__device__ int      g_flag[FLAG_CAP];                     // packed (b<<10)|h

// ---------------------------------------------------------------------------
// Helpers
// ---------------------------------------------------------------------------
__device__ __forceinline__ uint32_t smem_to_u32(const void* p) {
    uint32_t a;
    asm("{ .reg .u64 t; cvta.to.shared.u64 t, %1; cvt.u32.u64 %0, t; }" : "=r"(a) : "l"(p));
    return a;
}

// 2-way bf16 split of two fp32 values packed as bf16x2 (lo = elem a, hi = elem b).
__device__ __forceinline__ void split2(float a, float b, uint32_t& h, uint32_t& m) {
    uint32_t t;
    asm("cvt.rn.bf16x2.f32 %0, %1, %2;" : "=r"(t) : "f"(b), "f"(a));
    float fa = __uint_as_float(t << 16);
    float fb = __uint_as_float(t & 0xffff0000u);
    float ra = a - fa, rb = b - fb;
    h = t;
    asm("cvt.rn.bf16x2.f32 %0, %1, %2;" : "=r"(t) : "f"(rb), "f"(ra));
    m = t;
}

__device__ __forceinline__ void cp16(uint32_t dst, const void* src) {
    asm volatile("cp.async.cg.shared.global [%0], [%1], 16;" :: "r"(dst), "l"(src));
}
#define CP_COMMIT() asm volatile("cp.async.commit_group;" ::: "memory")
#define CP_WAIT1()  asm volatile("cp.async.wait_group 1;"  ::: "memory")

__device__ __forceinline__ void ldsm4(uint32_t* d, uint32_t addr) {
    asm volatile("ldmatrix.sync.aligned.m8n8.x4.shared.b16 {%0,%1,%2,%3}, [%4];"
                 : "=r"(d[0]), "=r"(d[1]), "=r"(d[2]), "=r"(d[3]) : "r"(addr));
}

__device__ __forceinline__ void mma16816(float* c, const uint32_t* a,
                                         uint32_t b0, uint32_t b1) {
    asm volatile(
        "mma.sync.aligned.m16n8k16.row.col.f32.bf16.bf16.f32 "
        "{%0,%1,%2,%3}, {%4,%5,%6,%7}, {%8,%9}, {%0,%1,%2,%3};"
        : "+f"(c[0]), "+f"(c[1]), "+f"(c[2]), "+f"(c[3])
        : "r"(a[0]), "r"(a[1]), "r"(a[2]), "r"(a[3]), "r"(b0), "r"(b1));
}

// ---------------------------------------------------------------------------
// Split kernels: fp32 -> (hi, mid) bf16
// ---------------------------------------------------------------------------
__global__ __launch_bounds__(256)
void split_x_kernel(const float* __restrict__ X)
{
    const size_t w = (size_t)blockIdx.x * 256 + threadIdx.x;
    if (w >= (size_t)M_DIM * K_DIM / 2) return;
    const float2 v = ((const float2*)X)[w];
    uint32_t h, m;
    split2(v.x, v.y, h, m);
    ((uint32_t*)g_Ah)[w] = h;
    ((uint32_t*)g_Am)[w] = m;
}

__global__ __launch_bounds__(256)
void split_w_kernel(const float* __restrict__ W1)
{
    if (blockIdx.x == 0 && threadIdx.x == 0) g_nflag = 0;
    const size_t w = (size_t)blockIdx.x * 256 + threadIdx.x;
    if (w >= (size_t)N_PAD * K_DIM / 2) return;
    const size_t row = (w * 2) / K_DIM;
    uint32_t h = 0, m = 0;
    if (row < N_DIM) {
        const float2 v = ((const float2*)W1)[w];
        split2(v.x, v.y, h, m);
    }
    ((uint32_t*)g_Bh)[w] = h;
    ((uint32_t*)g_Bm)[w] = m;
}

// ---------------------------------------------------------------------------
// GEMM + fused layer-1 LIF scan.
// BM=128 BN=128 BK=32, 256 threads (8 warps, 64x32 warp tiles), 3-stage
// cp.async pipeline, 2 CTAs/SM. Epilogue: h1 tile -> smem, run LIF over
// t (BM = 4 batches x 32 steps), emit bit-packed spk1 + borderline flags.
// ---------------------------------------------------------------------------
#define BM 128
#define BN 128
#define BK 32
#define STAGES 3
#define KTILES (K_DIM / BK)        // 200
#define SPLIT_SM 8192              // 128 rows x 64 B
#define STAGE_SM (4 * SPLIT_SM)    // 32768 B : Ah, Am, Bh, Bm
#define GEMM_SMEM (STAGES * STAGE_SM)  // 98304 B

#define HS 132                     // h1 smem row stride (floats), 128x132x4 = 67.6 KB

#define SWZ(r, c) (((r) << 6) + (((c) ^ (((r) >> 1) & 3)) << 4))

__global__ __launch_bounds__(256, 2)
void gemm_scan_fused(const float* __restrict__ bias)
{
    extern __shared__ char smem[];
    const uint32_t smb = smem_to_u32(smem);
    const int tid  = threadIdx.x;
    const int wid  = tid >> 5;
    const int lane = tid & 31;
    const int bm = blockIdx.y * BM;
    const int bn = blockIdx.x * BN;
    const int warp_m = (wid >> 2) * 64;   // 0 or 64
    const int warp_n = (wid & 3) * 32;    // 0,32,64,96

    // cp.async plan: 2048 16B-chunks per stage, 8 per thread.
    const __nv_bfloat16* bases[4] = { g_Ah, g_Am, g_Bh, g_Bm };
    uint32_t soff[8];
    const __nv_bfloat16* gptr[8];
#pragma unroll
    for (int i = 0; i < 8; ++i) {
        const int idx = tid + i * 256;
        const int s = idx >> 9;               // 0:Ah 1:Am 2:Bh 3:Bm
        const int r = (idx >> 2) & 127;
        const int c = idx & 3;
        soff[i] = (uint32_t)(s * SPLIT_SM + SWZ(r, c));
        const int rowg = (s < 2 ? bm : bn) + r;
        gptr[i] = bases[s] + (size_t)rowg * K_DIM + c * 8;
    }

    float acc[4][4][4];
#pragma unroll
    for (int mt = 0; mt < 4; ++mt)
#pragma unroll
        for (int nt = 0; nt < 4; ++nt)
#pragma unroll
            for (int e = 0; e < 4; ++e) acc[mt][nt][e] = 0.0f;

    // prologue: prefetch stages 0,1
#pragma unroll
    for (int s = 0; s < STAGES - 1; ++s) {
        const uint32_t stb = smb + s * STAGE_SM;
        const int koff = s * BK;
#pragma unroll
        for (int i = 0; i < 8; ++i) cp16(stb + soff[i], gptr[i] + koff);
        CP_COMMIT();
    }

    const int lr  = lane & 15;
    const int lch = lane >> 4;

    int bc = 0;               // compute stage buffer (kt % 3)
    int bp = STAGES - 1;      // prefetch buffer ((kt + 2) % 3)

    for (int kt = 0; kt < KTILES; ++kt) {
        CP_WAIT1();
        __syncthreads();

        const int nk = kt + STAGES - 1;
        if (nk < KTILES) {
            const uint32_t stb = smb + bp * STAGE_SM;
            const int koff = nk * BK;
#pragma unroll
            for (int i = 0; i < 8; ++i) cp16(stb + soff[i], gptr[i] + koff);
        }
        CP_COMMIT();

        const uint32_t stb = smb + bc * STAGE_SM;

#pragma unroll
        for (int k16 = 0; k16 < 2; ++k16) {
            const int c = k16 * 2 + lch;
            uint32_t af[2][4][4];
#pragma unroll
            for (int sp = 0; sp < 2; ++sp) {
                const uint32_t base = stb + sp * SPLIT_SM;
#pragma unroll
                for (int mt = 0; mt < 4; ++mt)
                    ldsm4(af[sp][mt], base + SWZ(warp_m + mt * 16 + lr, c));
            }
            uint32_t bf[2][2][4];
#pragma unroll
            for (int sp = 0; sp < 2; ++sp) {
                const uint32_t base = stb + (2 + sp) * SPLIT_SM;
#pragma unroll
                for (int np = 0; np < 2; ++np)
                    ldsm4(bf[sp][np], base + SWZ(warp_n + np * 16 + lr, c));
            }
            const int pa[3] = {0, 0, 1};
            const int pb[3] = {0, 1, 0};
#pragma unroll
            for (int p = 0; p < 3; ++p) {
#pragma unroll
                for (int mt = 0; mt < 4; ++mt) {
#pragma unroll
                    for (int nt = 0; nt < 4; ++nt) {
                        const int np = nt >> 1, sel = nt & 1;
                        mma16816(acc[mt][nt], af[pa[p]][mt],
                                 bf[pb[p]][np][sel], bf[pb[p]][np][sel + 2]);
                    }
                }
            }
        }

        bc = (bc == STAGES - 1) ? 0 : bc + 1;
        bp = (bp == STAGES - 1) ? 0 : bp + 1;
    }

    // ---- epilogue 1: acc (+bias) -> smem h1 tile [128 m][HS] ----
    __syncthreads();   // all stage reads done; reuse smem
    float* smh1 = (float*)smem;

    const int lrow = lane >> 2;
    const int lcol = (lane & 3) * 2;
#pragma unroll
    for (int nt = 0; nt < 4; ++nt) {
        const int nl = warp_n + nt * 8 + lcol;      // local n, 0..127
        const int ng = bn + nl;
        const float bx = (ng < N_DIM)     ? bias[ng]     : 0.0f;
        const float by = (ng + 1 < N_DIM) ? bias[ng + 1] : 0.0f;
#pragma unroll
        for (int mt = 0; mt < 4; ++mt) {
            const int m0 = warp_m + mt * 16 + lrow;  // local m
            smh1[(size_t)m0 * HS + nl]           = acc[mt][nt][0] + bx;
            smh1[(size_t)m0 * HS + nl + 1]       = acc[mt][nt][1] + by;
            smh1[(size_t)(m0 + 8) * HS + nl]     = acc[mt][nt][2] + bx;
            smh1[(size_t)(m0 + 8) * HS + nl + 1] = acc[mt][nt][3] + by;
        }
    }
    __syncthreads();

    // ---- epilogue 2: fused LIF scan over the 4 batches in this tile ----
    // thread -> h_local = tid & 127 ; half = tid >> 7 handles 2 batches.
    {
        const int hl    = tid & 127;
        const int half  = tid >> 7;
        const int hg    = bn + hl;
        const bool valid = (hg < N_DIM);
        const int b0    = (bm >> 5);              // first batch of tile

#pragma unroll
        for (int q = 0; q < 2; ++q) {
            const int bq = half * 2 + q;          // 0..3 within tile
            const int b  = b0 + bq;
            float mem = 0.0f;
            int flg = 0;
#pragma unroll 4
            for (int t = 0; t < TSTEPS; ++t) {
                const float cur = valid ? smh1[(size_t)(bq * 32 + t) * HS + hl] : 0.0f;
                const float mn  = (mem > THR_F) ? 0.0f : fmaf(BETA_F, mem, cur);
                mem = mn;
                const bool spk = valid && (mn > THR_F);
                if (valid && fabsf(mn - THR_F) < TOL_F) flg = 1;
                const uint32_t bits = __ballot_sync(0xffffffffu, spk);
                if (lane == 0)
                    g_spk1[(size_t)(b * TSTEPS + t) * 32 + (hg >> 5)] = bits;
            }
            if (flg) {
                const int i = atomicAdd(&g_nflag, 1);
                if (i < FLAG_CAP) g_flag[i] = (b << 10) | hg;
            }
        }
    }
}

// ---------------------------------------------------------------------------
// Fixup: exact fp32 recompute of flagged (b,h) pairs; rewrite spk1 bits.
// ---------------------------------------------------------------------------
__global__ __launch_bounds__(256)
void snn_fixup_kernel(const float* __restrict__ X,
                      const float* __restrict__ W1,
                      const float* __restrict__ b1)
{
    const int lane   = threadIdx.x & 31;
    const int gwarp  = (blockIdx.x * blockDim.x + threadIdx.x) >> 5;
    const int nwarps = (gridDim.x * blockDim.x) >> 5;
    int total = g_nflag;
    if (total > FLAG_CAP) total = FLAG_CAP;

    for (int e = gwarp; e < total; e += nwarps) {
        const int pair = g_flag[e];
        const int b = pair >> 10;
        const int h = pair & 1023;
        const float* wrow = W1 + (size_t)h * K_DIM;
        const float  bv   = b1[h];

        float mem = 0.0f;
        for (int t = 0; t < TSTEPS; t++) {
            const float* xrow = X + (size_t)(b * TSTEPS + t) * K_DIM;
            float s = 0.0f;
            for (int k = lane * 4; k < K_DIM; k += 128) {
                const float4 xv = *(const float4*)(xrow + k);
                const float4 wv = *(const float4*)(wrow + k);
                s = fmaf(xv.x, wv.x, s);
                s = fmaf(xv.y, wv.y, s);
                s = fmaf(xv.z, wv.z, s);
                s = fmaf(xv.w, wv.w, s);
            }
#pragma unroll
            for (int o = 16; o; o >>= 1) s += __shfl_xor_sync(0xffffffffu, s, o);

            const float cur = s + bv;
            const float mn  = (mem > THR_F) ? 0.0f : fmaf(BETA_F, mem, cur);
            mem = mn;
            if (lane == 0) {
                uint32_t* wptr = &g_spk1[(size_t)(b * TSTEPS + t) * 32 + (h >> 5)];
                const uint32_t bit = 1u << (h & 31);
                if (mn > THR_F) atomicOr(wptr, bit);
                else            atomicAnd(wptr, ~bit);
            }
        }
    }
}

// ---------------------------------------------------------------------------
// Layer-2: h2 = spk1 @ W2^T + b2, LIF, write spikes.
// ---------------------------------------------------------------------------
__global__ __launch_bounds__(256)
void snn_layer2_kernel(const float* __restrict__ W2,
                       const float* __restrict__ b2,
                       float* __restrict__ out)
{
    __shared__ float sW2[ACT][HID];
    __shared__ float sred[8][ACT];

    const int b    = blockIdx.x;
    const int tid  = threadIdx.x;
    const int lane = tid & 31;
    const int warp = tid >> 5;

    for (int i = tid; i < ACT * HID; i += 256)
        sW2[i / HID][i % HID] = W2[i];
    __syncthreads();

    float m2[ACT] = {0.f, 0.f, 0.f, 0.f};

    for (int t = 0; t < TSTEPS; t++) {
        const int m = b * TSTEPS + t;
        float acc0 = 0.f, acc1 = 0.f, acc2 = 0.f, acc3 = 0.f;

#pragma unroll
        for (int j = 0; j < 4; j++) {
            const int h = tid + j * 256;
            if (h < HID) {
                const uint32_t bits = g_spk1[m * 32 + (h >> 5)];
                const float spk = (float)((bits >> (h & 31)) & 1u);
                acc0 = fmaf(spk, sW2[0][h], acc0);
                acc1 = fmaf(spk, sW2[1][h], acc1);
                acc2 = fmaf(spk, sW2[2][h], acc2);
                acc3 = fmaf(spk, sW2[3][h], acc3);
            }
        }

#pragma unroll
        for (int o = 16; o; o >>= 1) {
            acc0 += __shfl_xor_sync(0xffffffffu, acc0, o);
            acc1 += __shfl_xor_sync(0xffffffffu, acc1, o);
            acc2 += __shfl_xor_sync(0xffffffffu, acc2, o);
            acc3 += __shfl_xor_sync(0xffffffffu, acc3, o);
        }
        if (lane == 0) {
            sred[warp][0] = acc0; sred[warp][1] = acc1;
            sred[warp][2] = acc2; sred[warp][3] = acc3;
        }
        __syncthreads();

        if (tid == 0) {
#pragma unroll
            for (int a = 0; a < ACT; a++) {
                float h2 = b2[a];
#pragma unroll
                for (int w = 0; w < 8; w++) h2 += sred[w][a];
                const float mn = (m2[a] > THR_F) ? 0.0f : fmaf(BETA_F, m2[a], h2);
                m2[a] = mn;
                out[((size_t)m) * ACT + a] = (mn > THR_F) ? 1.0f : 0.0f;
            }
        }
        __syncthreads();
    }
}

// ---------------------------------------------------------------------------
extern "C" void kernel_launch(void* const* d_in, const int* in_sizes, int n_in,
                              void* d_out, int out_size)
{
    const float* x  = (const float*)d_in[0];   // [128,32,6400]
    const float* W1 = (const float*)d_in[1];   // [1000,6400]
    const float* b1 = (const float*)d_in[2];   // [1000]
    const float* W2 = (const float*)d_in[3];   // [4,1000]
    const float* b2 = (const float*)d_in[4];   // [4]
    float* out = (float*)d_out;                // [128,32,4]

    cudaFuncSetAttribute(gemm_scan_fused,
                         cudaFuncAttributeMaxDynamicSharedMemorySize, GEMM_SMEM);

    {   // split X -> hi/mid bf16
        const int nwords = M_DIM * K_DIM / 2;
        split_x_kernel<<<(nwords + 255) / 256, 256>>>(x);
    }
    {   // split W1 (padded) -> hi/mid bf16 ; also resets flag counter
        const int nwords = N_PAD * K_DIM / 2;
        split_w_kernel<<<(nwords + 255) / 256, 256>>>(W1);
    }

    dim3 grid(N_PAD / BN, M_DIM / BM);         // (8, 32)
    gemm_scan_fused<<<grid, 256, GEMM_SMEM>>>(b1);

    snn_fixup_kernel<<<256, 256>>>(x, W1, b1);
    snn_layer2_kernel<<<BATCH, 256>>>(W2, b2, out);
}

// round 9
// speedup vs baseline: 2.6015x; 1.7521x over previous
#include <cuda_runtime.h>
#include <cuda_bf16.h>
#include <cstdint>

// ---------------------------------------------------------------------------
// Problem dims
// ---------------------------------------------------------------------------
#define BATCH   128
#define TSTEPS  32
#define D_DIM   6400
#define HID     1000
#define ACT     4
#define M_DIM   (BATCH * TSTEPS)   // 4096
#define N_DIM   HID                // 1000
#define N_PAD   1024
#define K_DIM   D_DIM              // 6400

#define BETA_F  0.99f
#define THR_F   1.0f
#define TOL_F   2.5e-4f            // borderline margin -> exact fp32 recompute
#define FLAG_CAP 65536

// ---------------------------------------------------------------------------
// Global scratch
// ---------------------------------------------------------------------------
__device__ __nv_bfloat16 g_Ah[M_DIM * K_DIM];             // 52.4 MB each
__device__ __nv_bfloat16 g_Am[M_DIM * K_DIM];
__device__ __nv_bfloat16 g_Bh[N_PAD * K_DIM];             // 13.1 MB each
__device__ __nv_bfloat16 g_Bm[N_PAD * K_DIM];

__device__ uint32_t g_spk1[M_DIM * 32];                   // bit-packed spk1
__device__ int      g_nflag;
__device__ int      g_flag[FLAG_CAP];                     // packed (b<<10)|h

// ---------------------------------------------------------------------------
// Helpers
// ---------------------------------------------------------------------------
__device__ __forceinline__ uint32_t smem_to_u32(const void* p) {
    uint32_t a;
    asm("{ .reg .u64 t; cvta.to.shared.u64 t, %1; cvt.u32.u64 %0, t; }" : "=r"(a) : "l"(p));
    return a;
}

// 2-way bf16 split of two fp32 values packed as bf16x2 (lo = elem a, hi = elem b).
__device__ __forceinline__ void split2(float a, float b, uint32_t& h, uint32_t& m) {
    uint32_t t;
    asm("cvt.rn.bf16x2.f32 %0, %1, %2;" : "=r"(t) : "f"(b), "f"(a));
    float fa = __uint_as_float(t << 16);
    float fb = __uint_as_float(t & 0xffff0000u);
    float ra = a - fa, rb = b - fb;
    h = t;
    asm("cvt.rn.bf16x2.f32 %0, %1, %2;" : "=r"(t) : "f"(rb), "f"(ra));
    m = t;
}

__device__ __forceinline__ void cp16(uint32_t dst, const void* src) {
    asm volatile("cp.async.cg.shared.global [%0], [%1], 16;" :: "r"(dst), "l"(src));
}
#define CP_COMMIT() asm volatile("cp.async.commit_group;" ::: "memory")
#define CP_WAIT1()  asm volatile("cp.async.wait_group 1;"  ::: "memory")

__device__ __forceinline__ void ldsm4(uint32_t* d, uint32_t addr) {
    asm volatile("ldmatrix.sync.aligned.m8n8.x4.shared.b16 {%0,%1,%2,%3}, [%4];"
                 : "=r"(d[0]), "=r"(d[1]), "=r"(d[2]), "=r"(d[3]) : "r"(addr));
}

__device__ __forceinline__ void mma16816(float* c, const uint32_t* a,
                                         uint32_t b0, uint32_t b1) {
    asm volatile(
        "mma.sync.aligned.m16n8k16.row.col.f32.bf16.bf16.f32 "
        "{%0,%1,%2,%3}, {%4,%5,%6,%7}, {%8,%9}, {%0,%1,%2,%3};"
        : "+f"(c[0]), "+f"(c[1]), "+f"(c[2]), "+f"(c[3])
        : "r"(a[0]), "r"(a[1]), "r"(a[2]), "r"(a[3]), "r"(b0), "r"(b1));
}

// ---------------------------------------------------------------------------
// Split kernels: fp32 -> (hi, mid) bf16
// ---------------------------------------------------------------------------
__global__ __launch_bounds__(256)
void split_x_kernel(const float* __restrict__ X)
{
    const size_t w = (size_t)blockIdx.x * 256 + threadIdx.x;
    if (w >= (size_t)M_DIM * K_DIM / 2) return;
    const float2 v = ((const float2*)X)[w];
    uint32_t h, m;
    split2(v.x, v.y, h, m);
    ((uint32_t*)g_Ah)[w] = h;
    ((uint32_t*)g_Am)[w] = m;
}

__global__ __launch_bounds__(256)
void split_w_kernel(const float* __restrict__ W1)
{
    if (blockIdx.x == 0 && threadIdx.x == 0) g_nflag = 0;
    const size_t w = (size_t)blockIdx.x * 256 + threadIdx.x;
    if (w >= (size_t)N_PAD * K_DIM / 2) return;
    const size_t row = (w * 2) / K_DIM;
    uint32_t h = 0, m = 0;
    if (row < N_DIM) {
        const float2 v = ((const float2*)W1)[w];
        split2(v.x, v.y, h, m);
    }
    ((uint32_t*)g_Bh)[w] = h;
    ((uint32_t*)g_Bm)[w] = m;
}

// ---------------------------------------------------------------------------
// GEMM + fused layer-1 LIF scan (unchanged from R8).
// ---------------------------------------------------------------------------
#define BM 128
#define BN 128
#define BK 32
#define STAGES 3
#define KTILES (K_DIM / BK)        // 200
#define SPLIT_SM 8192              // 128 rows x 64 B
#define STAGE_SM (4 * SPLIT_SM)    // 32768 B
#define GEMM_SMEM (STAGES * STAGE_SM)  // 98304 B

#define HS 132                     // h1 smem row stride (floats)

#define SWZ(r, c) (((r) << 6) + (((c) ^ (((r) >> 1) & 3)) << 4))

__global__ __launch_bounds__(256, 2)
void gemm_scan_fused(const float* __restrict__ bias)
{
    extern __shared__ char smem[];
    const uint32_t smb = smem_to_u32(smem);
    const int tid  = threadIdx.x;
    const int wid  = tid >> 5;
    const int lane = tid & 31;
    const int bm = blockIdx.y * BM;
    const int bn = blockIdx.x * BN;
    const int warp_m = (wid >> 2) * 64;
    const int warp_n = (wid & 3) * 32;

    const __nv_bfloat16* bases[4] = { g_Ah, g_Am, g_Bh, g_Bm };
    uint32_t soff[8];
    const __nv_bfloat16* gptr[8];
#pragma unroll
    for (int i = 0; i < 8; ++i) {
        const int idx = tid + i * 256;
        const int s = idx >> 9;
        const int r = (idx >> 2) & 127;
        const int c = idx & 3;
        soff[i] = (uint32_t)(s * SPLIT_SM + SWZ(r, c));
        const int rowg = (s < 2 ? bm : bn) + r;
        gptr[i] = bases[s] + (size_t)rowg * K_DIM + c * 8;
    }

    float acc[4][4][4];
#pragma unroll
    for (int mt = 0; mt < 4; ++mt)
#pragma unroll
        for (int nt = 0; nt < 4; ++nt)
#pragma unroll
            for (int e = 0; e < 4; ++e) acc[mt][nt][e] = 0.0f;

#pragma unroll
    for (int s = 0; s < STAGES - 1; ++s) {
        const uint32_t stb = smb + s * STAGE_SM;
        const int koff = s * BK;
#pragma unroll
        for (int i = 0; i < 8; ++i) cp16(stb + soff[i], gptr[i] + koff);
        CP_COMMIT();
    }

    const int lr  = lane & 15;
    const int lch = lane >> 4;

    int bc = 0;
    int bp = STAGES - 1;

    for (int kt = 0; kt < KTILES; ++kt) {
        CP_WAIT1();
        __syncthreads();

        const int nk = kt + STAGES - 1;
        if (nk < KTILES) {
            const uint32_t stb = smb + bp * STAGE_SM;
            const int koff = nk * BK;
#pragma unroll
            for (int i = 0; i < 8; ++i) cp16(stb + soff[i], gptr[i] + koff);
        }
        CP_COMMIT();

        const uint32_t stb = smb + bc * STAGE_SM;

#pragma unroll
        for (int k16 = 0; k16 < 2; ++k16) {
            const int c = k16 * 2 + lch;
            uint32_t af[2][4][4];
#pragma unroll
            for (int sp = 0; sp < 2; ++sp) {
                const uint32_t base = stb + sp * SPLIT_SM;
#pragma unroll
                for (int mt = 0; mt < 4; ++mt)
                    ldsm4(af[sp][mt], base + SWZ(warp_m + mt * 16 + lr, c));
            }
            uint32_t bf[2][2][4];
#pragma unroll
            for (int sp = 0; sp < 2; ++sp) {
                const uint32_t base = stb + (2 + sp) * SPLIT_SM;
#pragma unroll
                for (int np = 0; np < 2; ++np)
                    ldsm4(bf[sp][np], base + SWZ(warp_n + np * 16 + lr, c));
            }
            const int pa[3] = {0, 0, 1};
            const int pb[3] = {0, 1, 0};
#pragma unroll
            for (int p = 0; p < 3; ++p) {
#pragma unroll
                for (int mt = 0; mt < 4; ++mt) {
#pragma unroll
                    for (int nt = 0; nt < 4; ++nt) {
                        const int np = nt >> 1, sel = nt & 1;
                        mma16816(acc[mt][nt], af[pa[p]][mt],
                                 bf[pb[p]][np][sel], bf[pb[p]][np][sel + 2]);
                    }
                }
            }
        }

        bc = (bc == STAGES - 1) ? 0 : bc + 1;
        bp = (bp == STAGES - 1) ? 0 : bp + 1;
    }

    // ---- epilogue 1: acc (+bias) -> smem h1 tile [128 m][HS] ----
    __syncthreads();
    float* smh1 = (float*)smem;

    const int lrow = lane >> 2;
    const int lcol = (lane & 3) * 2;
#pragma unroll
    for (int nt = 0; nt < 4; ++nt) {
        const int nl = warp_n + nt * 8 + lcol;
        const int ng = bn + nl;
        const float bx = (ng < N_DIM)     ? bias[ng]     : 0.0f;
        const float by = (ng + 1 < N_DIM) ? bias[ng + 1] : 0.0f;
#pragma unroll
        for (int mt = 0; mt < 4; ++mt) {
            const int m0 = warp_m + mt * 16 + lrow;
            smh1[(size_t)m0 * HS + nl]           = acc[mt][nt][0] + bx;
            smh1[(size_t)m0 * HS + nl + 1]       = acc[mt][nt][1] + by;
            smh1[(size_t)(m0 + 8) * HS + nl]     = acc[mt][nt][2] + bx;
            smh1[(size_t)(m0 + 8) * HS + nl + 1] = acc[mt][nt][3] + by;
        }
    }
    __syncthreads();

    // ---- epilogue 2: fused LIF scan over the 4 batches in this tile ----
    {
        const int hl    = tid & 127;
        const int half  = tid >> 7;
        const int hg    = bn + hl;
        const bool valid = (hg < N_DIM);
        const int b0    = (bm >> 5);

#pragma unroll
        for (int q = 0; q < 2; ++q) {
            const int bq = half * 2 + q;
            const int b  = b0 + bq;
            float mem = 0.0f;
            int flg = 0;
#pragma unroll 4
            for (int t = 0; t < TSTEPS; ++t) {
                const float cur = valid ? smh1[(size_t)(bq * 32 + t) * HS + hl] : 0.0f;
                const float mn  = (mem > THR_F) ? 0.0f : fmaf(BETA_F, mem, cur);
                mem = mn;
                const bool spk = valid && (mn > THR_F);
                if (valid && fabsf(mn - THR_F) < TOL_F) flg = 1;
                const uint32_t bits = __ballot_sync(0xffffffffu, spk);
                if (lane == 0)
                    g_spk1[(size_t)(b * TSTEPS + t) * 32 + (hg >> 5)] = bits;
            }
            if (flg) {
                const int i = atomicAdd(&g_nflag, 1);
                if (i < FLAG_CAP) g_flag[i] = (b << 10) | hg;
            }
        }
    }
}

// ---------------------------------------------------------------------------
// Fixup v2: one CTA per flagged (b,h) entry (grid-stride).
// 8 warps x 4 timesteps each; the k-loop interleaves the 4 t-rows for MLP.
// Dots -> smem; thread 0 runs the 32-step recurrence and patches spk1.
// ---------------------------------------------------------------------------
__global__ __launch_bounds__(256)
void snn_fixup_kernel(const float* __restrict__ X,
                      const float* __restrict__ W1,
                      const float* __restrict__ b1)
{
    __shared__ float sdot[TSTEPS];

    const int tid  = threadIdx.x;
    const int lane = tid & 31;
    const int warp = tid >> 5;          // 0..7
    int total = g_nflag;
    if (total > FLAG_CAP) total = FLAG_CAP;

    for (int e = blockIdx.x; e < total; e += gridDim.x) {
        const int pair = g_flag[e];
        const int b = pair >> 10;
        const int h = pair & 1023;
        const float* wrow = W1 + (size_t)h * K_DIM;

        // warp handles t = warp*4 .. warp*4+3, interleaved k-loop
        const int t0 = warp * 4;
        const float* xr0 = X + (size_t)(b * TSTEPS + t0 + 0) * K_DIM;
        const float* xr1 = X + (size_t)(b * TSTEPS + t0 + 1) * K_DIM;
        const float* xr2 = X + (size_t)(b * TSTEPS + t0 + 2) * K_DIM;
        const float* xr3 = X + (size_t)(b * TSTEPS + t0 + 3) * K_DIM;

        float s0 = 0.f, s1 = 0.f, s2 = 0.f, s3 = 0.f;
        for (int k = lane * 4; k < K_DIM; k += 128) {
            const float4 wv = *(const float4*)(wrow + k);
            const float4 x0 = *(const float4*)(xr0 + k);
            const float4 x1 = *(const float4*)(xr1 + k);
            const float4 x2 = *(const float4*)(xr2 + k);
            const float4 x3 = *(const float4*)(xr3 + k);
            s0 = fmaf(x0.x, wv.x, s0); s0 = fmaf(x0.y, wv.y, s0);
            s0 = fmaf(x0.z, wv.z, s0); s0 = fmaf(x0.w, wv.w, s0);
            s1 = fmaf(x1.x, wv.x, s1); s1 = fmaf(x1.y, wv.y, s1);
            s1 = fmaf(x1.z, wv.z, s1); s1 = fmaf(x1.w, wv.w, s1);
            s2 = fmaf(x2.x, wv.x, s2); s2 = fmaf(x2.y, wv.y, s2);
            s2 = fmaf(x2.z, wv.z, s2); s2 = fmaf(x2.w, wv.w, s2);
            s3 = fmaf(x3.x, wv.x, s3); s3 = fmaf(x3.y, wv.y, s3);
            s3 = fmaf(x3.z, wv.z, s3); s3 = fmaf(x3.w, wv.w, s3);
        }
#pragma unroll
        for (int o = 16; o; o >>= 1) {
            s0 += __shfl_xor_sync(0xffffffffu, s0, o);
            s1 += __shfl_xor_sync(0xffffffffu, s1, o);
            s2 += __shfl_xor_sync(0xffffffffu, s2, o);
            s3 += __shfl_xor_sync(0xffffffffu, s3, o);
        }
        if (lane == 0) {
            sdot[t0 + 0] = s0;
            sdot[t0 + 1] = s1;
            sdot[t0 + 2] = s2;
            sdot[t0 + 3] = s3;
        }
        __syncthreads();

        if (tid == 0) {
            const float bv = b1[h];
            const uint32_t bit = 1u << (h & 31);
            float mem = 0.0f;
            for (int t = 0; t < TSTEPS; t++) {
                const float cur = sdot[t] + bv;
                const float mn  = (mem > THR_F) ? 0.0f : fmaf(BETA_F, mem, cur);
                mem = mn;
                uint32_t* wptr = &g_spk1[(size_t)(b * TSTEPS + t) * 32 + (h >> 5)];
                if (mn > THR_F) atomicOr(wptr, bit);
                else            atomicAnd(wptr, ~bit);
            }
        }
        __syncthreads();
    }
}

// ---------------------------------------------------------------------------
// Layer-2: h2 = spk1 @ W2^T + b2, LIF, write spikes.
// ---------------------------------------------------------------------------
__global__ __launch_bounds__(256)
void snn_layer2_kernel(const float* __restrict__ W2,
                       const float* __restrict__ b2,
                       float* __restrict__ out)
{
    __shared__ float sW2[ACT][HID];
    __shared__ float sred[8][ACT];

    const int b    = blockIdx.x;
    const int tid  = threadIdx.x;
    const int lane = tid & 31;
    const int warp = tid >> 5;

    for (int i = tid; i < ACT * HID; i += 256)
        sW2[i / HID][i % HID] = W2[i];
    __syncthreads();

    float m2[ACT] = {0.f, 0.f, 0.f, 0.f};

    for (int t = 0; t < TSTEPS; t++) {
        const int m = b * TSTEPS + t;
        float acc0 = 0.f, acc1 = 0.f, acc2 = 0.f, acc3 = 0.f;

#pragma unroll
        for (int j = 0; j < 4; j++) {
            const int h = tid + j * 256;
            if (h < HID) {
                const uint32_t bits = g_spk1[m * 32 + (h >> 5)];
                const float spk = (float)((bits >> (h & 31)) & 1u);
                acc0 = fmaf(spk, sW2[0][h], acc0);
                acc1 = fmaf(spk, sW2[1][h], acc1);
                acc2 = fmaf(spk, sW2[2][h], acc2);
                acc3 = fmaf(spk, sW2[3][h], acc3);
            }
        }

#pragma unroll
        for (int o = 16; o; o >>= 1) {
            acc0 += __shfl_xor_sync(0xffffffffu, acc0, o);
            acc1 += __shfl_xor_sync(0xffffffffu, acc1, o);
            acc2 += __shfl_xor_sync(0xffffffffu, acc2, o);
            acc3 += __shfl_xor_sync(0xffffffffu, acc3, o);
        }
        if (lane == 0) {
            sred[warp][0] = acc0; sred[warp][1] = acc1;
            sred[warp][2] = acc2; sred[warp][3] = acc3;
        }
        __syncthreads();

        if (tid == 0) {
#pragma unroll
            for (int a = 0; a < ACT; a++) {
                float h2 = b2[a];
#pragma unroll
                for (int w = 0; w < 8; w++) h2 += sred[w][a];
                const float mn = (m2[a] > THR_F) ? 0.0f : fmaf(BETA_F, m2[a], h2);
                m2[a] = mn;
                out[((size_t)m) * ACT + a] = (mn > THR_F) ? 1.0f : 0.0f;
            }
        }
        __syncthreads();
    }
}

// ---------------------------------------------------------------------------
extern "C" void kernel_launch(void* const* d_in, const int* in_sizes, int n_in,
                              void* d_out, int out_size)
{
    const float* x  = (const float*)d_in[0];   // [128,32,6400]
    const float* W1 = (const float*)d_in[1];   // [1000,6400]
    const float* b1 = (const float*)d_in[2];   // [1000]
    const float* W2 = (const float*)d_in[3];   // [4,1000]
    const float* b2 = (const float*)d_in[4];   // [4]
    float* out = (float*)d_out;                // [128,32,4]

    cudaFuncSetAttribute(gemm_scan_fused,
                         cudaFuncAttributeMaxDynamicSharedMemorySize, GEMM_SMEM);

    {   // split X -> hi/mid bf16
        const int nwords = M_DIM * K_DIM / 2;
        split_x_kernel<<<(nwords + 255) / 256, 256>>>(x);
    }
    {   // split W1 (padded) -> hi/mid bf16 ; also resets flag counter
        const int nwords = N_PAD * K_DIM / 2;
        split_w_kernel<<<(nwords + 255) / 256, 256>>>(W1);
    }

    dim3 grid(N_PAD / BN, M_DIM / BM);         // (8, 32)
    gemm_scan_fused<<<grid, 256, GEMM_SMEM>>>(b1);

    snn_fixup_kernel<<<256, 256>>>(x, W1, b1);
    snn_layer2_kernel<<<BATCH, 256>>>(W2, b2, out);
}

// round 10
// speedup vs baseline: 2.7590x; 1.0605x over previous
#include <cuda_runtime.h>
#include <cuda_bf16.h>
#include <cstdint>

// ---------------------------------------------------------------------------
// Problem dims
// ---------------------------------------------------------------------------
#define BATCH   128
#define TSTEPS  32
#define D_DIM   6400
#define HID     1000
#define ACT     4
#define M_DIM   (BATCH * TSTEPS)   // 4096
#define N_DIM   HID                // 1000
#define N_PAD   1024
#define K_DIM   D_DIM              // 6400

#define BETA_F  0.99f
#define THR_F   1.0f
#define TOL_F   2.5e-4f            // borderline margin -> exact fp32 recompute
#define FLAG_CAP 65536

// ---------------------------------------------------------------------------
// Global scratch
// ---------------------------------------------------------------------------
__device__ __nv_bfloat16 g_Ah[M_DIM * K_DIM];             // 52.4 MB each
__device__ __nv_bfloat16 g_Am[M_DIM * K_DIM];
__device__ __nv_bfloat16 g_Bh[N_PAD * K_DIM];             // 13.1 MB each
__device__ __nv_bfloat16 g_Bm[N_PAD * K_DIM];

__device__ uint32_t g_spk1[M_DIM * 32];                   // bit-packed spk1
__device__ int      g_nflag;
__device__ int      g_flag[FLAG_CAP];                     // packed (b<<10)|h

// ---------------------------------------------------------------------------
// Helpers
// ---------------------------------------------------------------------------
__device__ __forceinline__ uint32_t smem_to_u32(const void* p) {
    uint32_t a;
    asm("{ .reg .u64 t; cvta.to.shared.u64 t, %1; cvt.u32.u64 %0, t; }" : "=r"(a) : "l"(p));
    return a;
}

// 2-way bf16 split of two fp32 values packed as bf16x2 (lo = elem a, hi = elem b).
__device__ __forceinline__ void split2(float a, float b, uint32_t& h, uint32_t& m) {
    uint32_t t;
    asm("cvt.rn.bf16x2.f32 %0, %1, %2;" : "=r"(t) : "f"(b), "f"(a));
    float fa = __uint_as_float(t << 16);
    float fb = __uint_as_float(t & 0xffff0000u);
    float ra = a - fa, rb = b - fb;
    h = t;
    asm("cvt.rn.bf16x2.f32 %0, %1, %2;" : "=r"(t) : "f"(rb), "f"(ra));
    m = t;
}

__device__ __forceinline__ void cp16(uint32_t dst, const void* src) {
    asm volatile("cp.async.cg.shared.global [%0], [%1], 16;" :: "r"(dst), "l"(src));
}
#define CP_COMMIT() asm volatile("cp.async.commit_group;" ::: "memory")
#define CP_WAIT1()  asm volatile("cp.async.wait_group 1;"  ::: "memory")

__device__ __forceinline__ void ldsm4(uint32_t* d, uint32_t addr) {
    asm volatile("ldmatrix.sync.aligned.m8n8.x4.shared.b16 {%0,%1,%2,%3}, [%4];"
                 : "=r"(d[0]), "=r"(d[1]), "=r"(d[2]), "=r"(d[3]) : "r"(addr));
}

__device__ __forceinline__ void mma16816(float* c, const uint32_t* a,
                                         uint32_t b0, uint32_t b1) {
    asm volatile(
        "mma.sync.aligned.m16n8k16.row.col.f32.bf16.bf16.f32 "
        "{%0,%1,%2,%3}, {%4,%5,%6,%7}, {%8,%9}, {%0,%1,%2,%3};"
        : "+f"(c[0]), "+f"(c[1]), "+f"(c[2]), "+f"(c[3])
        : "r"(a[0]), "r"(a[1]), "r"(a[2]), "r"(a[3]), "r"(b0), "r"(b1));
}

// ---------------------------------------------------------------------------
// Split kernels: fp32 -> (hi, mid) bf16
// ---------------------------------------------------------------------------
__global__ __launch_bounds__(256)
void split_x_kernel(const float* __restrict__ X)
{
    const size_t w = (size_t)blockIdx.x * 256 + threadIdx.x;
    if (w >= (size_t)M_DIM * K_DIM / 2) return;
    const float2 v = ((const float2*)X)[w];
    uint32_t h, m;
    split2(v.x, v.y, h, m);
    ((uint32_t*)g_Ah)[w] = h;
    ((uint32_t*)g_Am)[w] = m;
}

__global__ __launch_bounds__(256)
void split_w_kernel(const float* __restrict__ W1)
{
    if (blockIdx.x == 0 && threadIdx.x == 0) g_nflag = 0;
    const size_t w = (size_t)blockIdx.x * 256 + threadIdx.x;
    if (w >= (size_t)N_PAD * K_DIM / 2) return;
    const size_t row = (w * 2) / K_DIM;
    uint32_t h = 0, m = 0;
    if (row < N_DIM) {
        const float2 v = ((const float2*)W1)[w];
        split2(v.x, v.y, h, m);
    }
    ((uint32_t*)g_Bh)[w] = h;
    ((uint32_t*)g_Bm)[w] = m;
}

// ---------------------------------------------------------------------------
// GEMM + fused layer-1 LIF scan.
// BM=128 BN=128 BK=32, 256 threads (8 warps, 64x32 warp tiles), 3-stage
// cp.async pipeline, 2 CTAs/SM.  Register-pressure-aware mainloop:
// passes sequenced hh -> hm -> mh with the A-fragment array reused
// (hi then mid), compact 4-pointer load plan.
// ---------------------------------------------------------------------------
#define BM 128
#define BN 128
#define BK 32
#define STAGES 3
#define KTILES (K_DIM / BK)        // 200
#define SPLIT_SM 8192              // 128 rows x 64 B
#define STAGE_SM (4 * SPLIT_SM)    // 32768 B
#define GEMM_SMEM (STAGES * STAGE_SM)  // 98304 B

#define HS 132                     // h1 smem row stride (floats)

#define SWZ(r, c) (((r) << 6) + (((c) ^ (((r) >> 1) & 3)) << 4))

__global__ __launch_bounds__(256, 2)
void gemm_scan_fused(const float* __restrict__ bias)
{
    extern __shared__ char smem[];
    const uint32_t smb = smem_to_u32(smem);
    const int tid  = threadIdx.x;
    const int wid  = tid >> 5;
    const int lane = tid & 31;
    const int bm = blockIdx.y * BM;
    const int bn = blockIdx.x * BN;
    const int warp_m = (wid >> 2) * 64;
    const int warp_n = (wid & 3) * 32;

    // Compact load plan: 4 running pointers + 4 smem offsets.
    // Thread covers rows r0 and r0+64 (chunk cc) of each of the 4 arrays.
    const int r0 = tid >> 2;             // 0..63
    const int cc = tid & 3;
    const __nv_bfloat16* gp0 = g_Ah + (size_t)(bm + r0) * K_DIM + cc * 8;
    const __nv_bfloat16* gp1 = g_Am + (size_t)(bm + r0) * K_DIM + cc * 8;
    const __nv_bfloat16* gp2 = g_Bh + (size_t)(bn + r0) * K_DIM + cc * 8;
    const __nv_bfloat16* gp3 = g_Bm + (size_t)(bn + r0) * K_DIM + cc * 8;
    const uint32_t sw = SWZ(r0, cc);     // SWZ(r0+64,cc) = sw + 4096
    const uint32_t so0 = 0 * SPLIT_SM + sw;
    const uint32_t so1 = 1 * SPLIT_SM + sw;
    const uint32_t so2 = 2 * SPLIT_SM + sw;
    const uint32_t so3 = 3 * SPLIT_SM + sw;
    const size_t ROWOFF = (size_t)64 * K_DIM;   // +64 rows in gmem

#define ISSUE_STAGE(stb) do {                                  \
        cp16((stb) + so0,        gp0);                         \
        cp16((stb) + so0 + 4096, gp0 + ROWOFF);                \
        cp16((stb) + so1,        gp1);                         \
        cp16((stb) + so1 + 4096, gp1 + ROWOFF);                \
        cp16((stb) + so2,        gp2);                         \
        cp16((stb) + so2 + 4096, gp2 + ROWOFF);                \
        cp16((stb) + so3,        gp3);                         \
        cp16((stb) + so3 + 4096, gp3 + ROWOFF);                \
        gp0 += BK; gp1 += BK; gp2 += BK; gp3 += BK;            \
    } while (0)

    float acc[4][4][4];
#pragma unroll
    for (int mt = 0; mt < 4; ++mt)
#pragma unroll
        for (int nt = 0; nt < 4; ++nt)
#pragma unroll
            for (int e = 0; e < 4; ++e) acc[mt][nt][e] = 0.0f;

    // prologue: prefetch stages 0,1
#pragma unroll
    for (int s = 0; s < STAGES - 1; ++s) {
        ISSUE_STAGE(smb + s * STAGE_SM);
        CP_COMMIT();
    }

    const int lr  = lane & 15;
    const int lch = lane >> 4;

    int bc = 0;
    int bp = STAGES - 1;

    for (int kt = 0; kt < KTILES; ++kt) {
        CP_WAIT1();
        __syncthreads();

        if (kt + STAGES - 1 < KTILES) {
            ISSUE_STAGE(smb + bp * STAGE_SM);
        }
        CP_COMMIT();

        const uint32_t stb = smb + bc * STAGE_SM;

#pragma unroll
        for (int k16 = 0; k16 < 2; ++k16) {
            const int c = k16 * 2 + lch;

            uint32_t af[4][4];       // reused: hi then mid
            uint32_t bh[2][4];
            uint32_t bmf[2][4];

            // A-hi, B-hi, B-mid fragments
#pragma unroll
            for (int mt = 0; mt < 4; ++mt)
                ldsm4(af[mt], stb + 0 * SPLIT_SM + SWZ(warp_m + mt * 16 + lr, c));
#pragma unroll
            for (int np = 0; np < 2; ++np)
                ldsm4(bh[np],  stb + 2 * SPLIT_SM + SWZ(warp_n + np * 16 + lr, c));
#pragma unroll
            for (int np = 0; np < 2; ++np)
                ldsm4(bmf[np], stb + 3 * SPLIT_SM + SWZ(warp_n + np * 16 + lr, c));

            // pass hh: A-hi x B-hi
#pragma unroll
            for (int mt = 0; mt < 4; ++mt)
#pragma unroll
                for (int nt = 0; nt < 4; ++nt) {
                    const int np = nt >> 1, sel = nt & 1;
                    mma16816(acc[mt][nt], af[mt], bh[np][sel], bh[np][sel + 2]);
                }

            // pass hm: A-hi x B-mid
#pragma unroll
            for (int mt = 0; mt < 4; ++mt)
#pragma unroll
                for (int nt = 0; nt < 4; ++nt) {
                    const int np = nt >> 1, sel = nt & 1;
                    mma16816(acc[mt][nt], af[mt], bmf[np][sel], bmf[np][sel + 2]);
                }

            // A-mid overwrites af (WAR caps fragment liveness)
#pragma unroll
            for (int mt = 0; mt < 4; ++mt)
                ldsm4(af[mt], stb + 1 * SPLIT_SM + SWZ(warp_m + mt * 16 + lr, c));

            // pass mh: A-mid x B-hi
#pragma unroll
            for (int mt = 0; mt < 4; ++mt)
#pragma unroll
                for (int nt = 0; nt < 4; ++nt) {
                    const int np = nt >> 1, sel = nt & 1;
                    mma16816(acc[mt][nt], af[mt], bh[np][sel], bh[np][sel + 2]);
                }
        }

        bc = (bc == STAGES - 1) ? 0 : bc + 1;
        bp = (bp == STAGES - 1) ? 0 : bp + 1;
    }

    // ---- epilogue 1: acc (+bias) -> smem h1 tile [128 m][HS] ----
    __syncthreads();
    float* smh1 = (float*)smem;

    const int lrow = lane >> 2;
    const int lcol = (lane & 3) * 2;
#pragma unroll
    for (int nt = 0; nt < 4; ++nt) {
        const int nl = warp_n + nt * 8 + lcol;
        const int ng = bn + nl;
        const float bx = (ng < N_DIM)     ? bias[ng]     : 0.0f;
        const float by = (ng + 1 < N_DIM) ? bias[ng + 1] : 0.0f;
#pragma unroll
        for (int mt = 0; mt < 4; ++mt) {
            const int m0 = warp_m + mt * 16 + lrow;
            smh1[(size_t)m0 * HS + nl]           = acc[mt][nt][0] + bx;
            smh1[(size_t)m0 * HS + nl + 1]       = acc[mt][nt][1] + by;
            smh1[(size_t)(m0 + 8) * HS + nl]     = acc[mt][nt][2] + bx;
            smh1[(size_t)(m0 + 8) * HS + nl + 1] = acc[mt][nt][3] + by;
        }
    }
    __syncthreads();

    // ---- epilogue 2: fused LIF scan over the 4 batches in this tile ----
    {
        const int hl    = tid & 127;
        const int half  = tid >> 7;
        const int hg    = bn + hl;
        const bool valid = (hg < N_DIM);
        const int b0    = (bm >> 5);

#pragma unroll
        for (int q = 0; q < 2; ++q) {
            const int bq = half * 2 + q;
            const int b  = b0 + bq;
            float mem = 0.0f;
            int flg = 0;
#pragma unroll 4
            for (int t = 0; t < TSTEPS; ++t) {
                const float cur = valid ? smh1[(size_t)(bq * 32 + t) * HS + hl] : 0.0f;
                const float mn  = (mem > THR_F) ? 0.0f : fmaf(BETA_F, mem, cur);
                mem = mn;
                const bool spk = valid && (mn > THR_F);
                if (valid && fabsf(mn - THR_F) < TOL_F) flg = 1;
                const uint32_t bits = __ballot_sync(0xffffffffu, spk);
                if (lane == 0)
                    g_spk1[(size_t)(b * TSTEPS + t) * 32 + (hg >> 5)] = bits;
            }
            if (flg) {
                const int i = atomicAdd(&g_nflag, 1);
                if (i < FLAG_CAP) g_flag[i] = (b << 10) | hg;
            }
        }
    }
#undef ISSUE_STAGE
}

// ---------------------------------------------------------------------------
// Fixup v3: one CTA per flagged (b,h) entry (grid-stride), 512 threads.
// 16 warps x 2 timesteps; k-loop unrolled x2 for MLP. Dots -> smem;
// thread 0 runs the 32-step recurrence and patches spk1 bits.
// ---------------------------------------------------------------------------
__global__ __launch_bounds__(512)
void snn_fixup_kernel(const float* __restrict__ X,
                      const float* __restrict__ W1,
                      const float* __restrict__ b1)
{
    __shared__ float sdot[TSTEPS];

    const int tid  = threadIdx.x;
    const int lane = tid & 31;
    const int warp = tid >> 5;          // 0..15
    int total = g_nflag;
    if (total > FLAG_CAP) total = FLAG_CAP;

    for (int e = blockIdx.x; e < total; e += gridDim.x) {
        const int pair = g_flag[e];
        const int b = pair >> 10;
        const int h = pair & 1023;
        const float* wrow = W1 + (size_t)h * K_DIM;

        // warp handles t = warp*2, warp*2+1
        const int t0 = warp * 2;
        const float* xr0 = X + (size_t)(b * TSTEPS + t0 + 0) * K_DIM;
        const float* xr1 = X + (size_t)(b * TSTEPS + t0 + 1) * K_DIM;

        float s0 = 0.f, s1 = 0.f;
#pragma unroll 2
        for (int k = lane * 4; k < K_DIM; k += 128) {
            const float4 wv = *(const float4*)(wrow + k);
            const float4 x0 = *(const float4*)(xr0 + k);
            const float4 x1 = *(const float4*)(xr1 + k);
            s0 = fmaf(x0.x, wv.x, s0); s0 = fmaf(x0.y, wv.y, s0);
            s0 = fmaf(x0.z, wv.z, s0); s0 = fmaf(x0.w, wv.w, s0);
            s1 = fmaf(x1.x, wv.x, s1); s1 = fmaf(x1.y, wv.y, s1);
            s1 = fmaf(x1.z, wv.z, s1); s1 = fmaf(x1.w, wv.w, s1);
        }
#pragma unroll
        for (int o = 16; o; o >>= 1) {
            s0 += __shfl_xor_sync(0xffffffffu, s0, o);
            s1 += __shfl_xor_sync(0xffffffffu, s1, o);
        }
        if (lane == 0) {
            sdot[t0 + 0] = s0;
            sdot[t0 + 1] = s1;
        }
        __syncthreads();

        if (tid == 0) {
            const float bv = b1[h];
            const uint32_t bit = 1u << (h & 31);
            float mem = 0.0f;
            for (int t = 0; t < TSTEPS; t++) {
                const float cur = sdot[t] + bv;
                const float mn  = (mem > THR_F) ? 0.0f : fmaf(BETA_F, mem, cur);
                mem = mn;
                uint32_t* wptr = &g_spk1[(size_t)(b * TSTEPS + t) * 32 + (h >> 5)];
                if (mn > THR_F) atomicOr(wptr, bit);
                else            atomicAnd(wptr, ~bit);
            }
        }
        __syncthreads();
    }
}

// ---------------------------------------------------------------------------
// Layer-2: h2 = spk1 @ W2^T + b2, LIF, write spikes.
// ---------------------------------------------------------------------------
__global__ __launch_bounds__(256)
void snn_layer2_kernel(const float* __restrict__ W2,
                       const float* __restrict__ b2,
                       float* __restrict__ out)
{
    __shared__ float sW2[ACT][HID];
    __shared__ float sred[8][ACT];

    const int b    = blockIdx.x;
    const int tid  = threadIdx.x;
    const int lane = tid & 31;
    const int warp = tid >> 5;

    for (int i = tid; i < ACT * HID; i += 256)
        sW2[i / HID][i % HID] = W2[i];
    __syncthreads();

    float m2[ACT] = {0.f, 0.f, 0.f, 0.f};

    for (int t = 0; t < TSTEPS; t++) {
        const int m = b * TSTEPS + t;
        float acc0 = 0.f, acc1 = 0.f, acc2 = 0.f, acc3 = 0.f;

#pragma unroll
        for (int j = 0; j < 4; j++) {
            const int h = tid + j * 256;
            if (h < HID) {
                const uint32_t bits = g_spk1[m * 32 + (h >> 5)];
                const float spk = (float)((bits >> (h & 31)) & 1u);
                acc0 = fmaf(spk, sW2[0][h], acc0);
                acc1 = fmaf(spk, sW2[1][h], acc1);
                acc2 = fmaf(spk, sW2[2][h], acc2);
                acc3 = fmaf(spk, sW2[3][h], acc3);
            }
        }

#pragma unroll
        for (int o = 16; o; o >>= 1) {
            acc0 += __shfl_xor_sync(0xffffffffu, acc0, o);
            acc1 += __shfl_xor_sync(0xffffffffu, acc1, o);
            acc2 += __shfl_xor_sync(0xffffffffu, acc2, o);
            acc3 += __shfl_xor_sync(0xffffffffu, acc3, o);
        }
        if (lane == 0) {
            sred[warp][0] = acc0; sred[warp][1] = acc1;
            sred[warp][2] = acc2; sred[warp][3] = acc3;
        }
        __syncthreads();

        if (tid == 0) {
#pragma unroll
            for (int a = 0; a < ACT; a++) {
                float h2 = b2[a];
#pragma unroll
                for (int w = 0; w < 8; w++) h2 += sred[w][a];
                const float mn = (m2[a] > THR_F) ? 0.0f : fmaf(BETA_F, m2[a], h2);
                m2[a] = mn;
                out[((size_t)m) * ACT + a] = (mn > THR_F) ? 1.0f : 0.0f;
            }
        }
        __syncthreads();
    }
}

// ---------------------------------------------------------------------------
extern "C" void kernel_launch(void* const* d_in, const int* in_sizes, int n_in,
                              void* d_out, int out_size)
{
    const float* x  = (const float*)d_in[0];   // [128,32,6400]
    const float* W1 = (const float*)d_in[1];   // [1000,6400]
    const float* b1 = (const float*)d_in[2];   // [1000]
    const float* W2 = (const float*)d_in[3];   // [4,1000]
    const float* b2 = (const float*)d_in[4];   // [4]
    float* out = (float*)d_out;                // [128,32,4]

    cudaFuncSetAttribute(gemm_scan_fused,
                         cudaFuncAttributeMaxDynamicSharedMemorySize, GEMM_SMEM);

    {   // split X -> hi/mid bf16
        const int nwords = M_DIM * K_DIM / 2;
        split_x_kernel<<<(nwords + 255) / 256, 256>>>(x);
    }
    {   // split W1 (padded) -> hi/mid bf16 ; also resets flag counter
        const int nwords = N_PAD * K_DIM / 2;
        split_w_kernel<<<(nwords + 255) / 256, 256>>>(W1);
    }

    dim3 grid(N_PAD / BN, M_DIM / BM);         // (8, 32)
    gemm_scan_fused<<<grid, 256, GEMM_SMEM>>>(b1);

    snn_fixup_kernel<<<256, 512>>>(x, W1, b1);
    snn_layer2_kernel<<<BATCH, 256>>>(W2, b2, out);
}